// round 2
// baseline (speedup 1.0000x reference)
#include <cuda_runtime.h>
#include <cuda_bf16.h>
#include <stdint.h>

// Problem shape (fixed by the dataset)
#define B_DIM   8192
#define IN_DIM  1024
#define OUT_DIM 4096

// out[b,o] = ||x_b||^2 - 2 * (x @ W)[b,o] + ||w_:,o||^2

// Scratch (no cudaMalloc allowed)
__device__ float g_xsq[B_DIM];
__device__ float g_wsq[OUT_DIM];

// ---------------------------------------------------------------------------
// Kernel 1: row sums of squares of x  (one warp per row)
// ---------------------------------------------------------------------------
__global__ void rowsq_kernel(const float* __restrict__ x, float* __restrict__ xsq) {
    int row  = blockIdx.x * 8 + (threadIdx.x >> 5);
    int lane = threadIdx.x & 31;
    const float4* p = (const float4*)(x + (size_t)row * IN_DIM);
    float s = 0.f;
#pragma unroll
    for (int i = 0; i < IN_DIM / 128; i++) {   // 1024/4 float4 / 32 lanes = 8 iters
        float4 v = p[lane + i * 32];
        s += v.x * v.x + v.y * v.y + v.z * v.z + v.w * v.w;
    }
#pragma unroll
    for (int o = 16; o; o >>= 1) s += __shfl_xor_sync(0xFFFFFFFFu, s, o);
    if (lane == 0) xsq[row] = s;
}

// ---------------------------------------------------------------------------
// Kernel 2: column sums of squares of W (one thread per output column)
// ---------------------------------------------------------------------------
__global__ void colsq_kernel(const float* __restrict__ w, float* __restrict__ wsq) {
    int o = blockIdx.x * blockDim.x + threadIdx.x;
    float s = 0.f;
#pragma unroll 16
    for (int i = 0; i < IN_DIM; i++) {
        float v = w[(size_t)i * OUT_DIM + o];
        s += v * v;
    }
    wsq[o] = s;
}

// ---------------------------------------------------------------------------
// Kernel 3: tiled fp32 GEMM with fused distance epilogue
//   BM=128, BN=128, BK=16, 256 threads, 8x8 micro-tile per thread
// ---------------------------------------------------------------------------
#define BM 128
#define BN 128
#define BK 16
#define TM 8
#define TN 8
#define PAD 4

__global__ __launch_bounds__(256, 2)
void rbf_gemm_kernel(const float* __restrict__ X,   // [B, IN]
                     const float* __restrict__ W,   // [IN, OUT]
                     const float* __restrict__ xsq, // [B]
                     const float* __restrict__ wsq, // [OUT]
                     float* __restrict__ out)       // [B, OUT]
{
    __shared__ float As[BK][BM + PAD];   // transposed A tile
    __shared__ float Bs[BK][BN];

    const int bx  = blockIdx.x;          // N tile index
    const int by  = blockIdx.y;          // M tile index
    const int tid = threadIdx.x;
    const int tcol = tid & 15;           // 0..15
    const int trow = tid >> 4;           // 0..15

    const float* Aptr = X + (size_t)(by * BM) * IN_DIM;
    const float* Bptr = W + (size_t)(bx * BN);

    float acc[TM][TN];
#pragma unroll
    for (int i = 0; i < TM; i++)
#pragma unroll
        for (int j = 0; j < TN; j++) acc[i][j] = 0.f;

    for (int k0 = 0; k0 < IN_DIM; k0 += BK) {
        // --- load A tile: 128 rows x 16 cols = 512 float4, 2 per thread ---
#pragma unroll
        for (int l = tid; l < 512; l += 256) {
            int r  = l >> 2;       // row within tile 0..127
            int c4 = l & 3;        // float4 index within the 16-wide row
            float4 v = *(const float4*)(Aptr + (size_t)r * IN_DIM + k0 + c4 * 4);
            As[c4 * 4 + 0][r] = v.x;
            As[c4 * 4 + 1][r] = v.y;
            As[c4 * 4 + 2][r] = v.z;
            As[c4 * 4 + 3][r] = v.w;
        }
        // --- load B tile: 16 rows x 128 cols = 512 float4, 2 per thread ---
#pragma unroll
        for (int l = tid; l < 512; l += 256) {
            int r  = l >> 5;       // row within tile 0..15
            int c4 = l & 31;       // float4 index within the 128-wide row
            float4 v = *(const float4*)(Bptr + (size_t)(k0 + r) * OUT_DIM + c4 * 4);
            *(float4*)&Bs[r][c4 * 4] = v;
        }
        __syncthreads();

#pragma unroll
        for (int kk = 0; kk < BK; kk++) {
            float a[TM], b[TN];
#pragma unroll
            for (int i = 0; i < TM; i++) a[i] = As[kk][trow * TM + i];
#pragma unroll
            for (int j = 0; j < TN; j += 4) {
                float4 v = *(const float4*)&Bs[kk][tcol * TN + j];
                b[j] = v.x; b[j + 1] = v.y; b[j + 2] = v.z; b[j + 3] = v.w;
            }
#pragma unroll
            for (int i = 0; i < TM; i++)
#pragma unroll
                for (int j = 0; j < TN; j++)
                    acc[i][j] = fmaf(a[i], b[j], acc[i][j]);
        }
        __syncthreads();
    }

    // --- epilogue: out = xsq + wsq - 2*acc ---
    const int m0 = by * BM + trow * TM;
    const int n0 = bx * BN + tcol * TN;
    float4 w0 = *(const float4*)(wsq + n0);
    float4 w1 = *(const float4*)(wsq + n0 + 4);
#pragma unroll
    for (int i = 0; i < TM; i++) {
        float xs = xsq[m0 + i];
        float* orow = out + (size_t)(m0 + i) * OUT_DIM + n0;
        float4 r0, r1;
        r0.x = xs + w0.x - 2.f * acc[i][0];
        r0.y = xs + w0.y - 2.f * acc[i][1];
        r0.z = xs + w0.z - 2.f * acc[i][2];
        r0.w = xs + w0.w - 2.f * acc[i][3];
        r1.x = xs + w1.x - 2.f * acc[i][4];
        r1.y = xs + w1.y - 2.f * acc[i][5];
        r1.z = xs + w1.z - 2.f * acc[i][6];
        r1.w = xs + w1.w - 2.f * acc[i][7];
        *(float4*)orow       = r0;
        *(float4*)(orow + 4) = r1;
    }
}

// ---------------------------------------------------------------------------
extern "C" void kernel_launch(void* const* d_in, const int* in_sizes, int n_in,
                              void* d_out, int out_size) {
    const float* x = (const float*)d_in[0];   // [8192, 1024]
    const float* w = (const float*)d_in[1];   // [1024, 4096]
    float* out     = (float*)d_out;           // [8192, 4096]

    float* xsq;  cudaGetSymbolAddress((void**)&xsq, g_xsq);
    float* wsq;  cudaGetSymbolAddress((void**)&wsq, g_wsq);

    rowsq_kernel<<<B_DIM / 8, 256>>>(x, xsq);
    colsq_kernel<<<OUT_DIM / 256, 256>>>(w, wsq);

    dim3 grid(OUT_DIM / BN, B_DIM / BM);      // 32 x 64 = 2048 blocks
    rbf_gemm_kernel<<<grid, 256>>>(x, w, xsq, wsq, out);
}

// round 4
// speedup vs baseline: 6.3090x; 6.3090x over previous
#include <cuda_runtime.h>
#include <cuda_bf16.h>
#include <stdint.h>

#define B_DIM   8192
#define IN_DIM  1024
#define OUT_DIM 4096

// out[b,o] = ||x_b||^2 - 2 * (x @ W)[b,o] + ||w_:,o||^2

// ---------------------------------------------------------------------------
// Static device scratch (no cudaMalloc allowed)
// ---------------------------------------------------------------------------
__device__ float         g_xsq[B_DIM];
__device__ float         g_wsq[OUT_DIM];
__device__ __nv_bfloat16 g_xb[(size_t)B_DIM * IN_DIM];    // X in bf16    (16 MB)
__device__ __nv_bfloat16 g_wt[(size_t)OUT_DIM * IN_DIM];  // W^T in bf16  ( 8 MB)

// ---------------------------------------------------------------------------
// Helpers (plain sm_80+ PTX only — no arch-'a' features; toolchain lowers
// through compute_103 which rejects tcgen05/TMEM)
// ---------------------------------------------------------------------------
__device__ __forceinline__ uint32_t smem_u32(const void* p) {
    uint32_t a;
    asm("{ .reg .u64 t; cvta.to.shared.u64 t, %1; cvt.u32.u64 %0, t; }" : "=r"(a) : "l"(p));
    return a;
}
__device__ __forceinline__ void cp16(uint32_t dst, const void* src) {
    asm volatile("cp.async.cg.shared.global [%0], [%1], 16;" :: "r"(dst), "l"(src));
}
#define CP_COMMIT() asm volatile("cp.async.commit_group;" ::: "memory")
#define CP_WAIT(n)  asm volatile("cp.async.wait_group %0;" :: "n"(n) : "memory")

__device__ __forceinline__ void ldsm_x4(uint32_t* r, uint32_t addr) {
    asm volatile("ldmatrix.sync.aligned.m8n8.x4.shared.b16 {%0,%1,%2,%3}, [%4];"
                 : "=r"(r[0]), "=r"(r[1]), "=r"(r[2]), "=r"(r[3]) : "r"(addr));
}
__device__ __forceinline__ void mma16816(float* c, const uint32_t* a, const uint32_t* b) {
    asm volatile("mma.sync.aligned.m16n8k16.row.col.f32.bf16.bf16.f32 "
                 "{%0,%1,%2,%3}, {%4,%5,%6,%7}, {%8,%9}, {%0,%1,%2,%3};"
                 : "+f"(c[0]), "+f"(c[1]), "+f"(c[2]), "+f"(c[3])
                 : "r"(a[0]), "r"(a[1]), "r"(a[2]), "r"(a[3]), "r"(b[0]), "r"(b[1]));
}

// ---------------------------------------------------------------------------
// Pre-pass 1: row sums of squares of x (fp32-exact) + convert x -> bf16
// ---------------------------------------------------------------------------
__global__ void rowsq_conv_kernel(const float* __restrict__ x,
                                  float* __restrict__ xsq,
                                  __nv_bfloat16* __restrict__ xb) {
    int row  = blockIdx.x * 8 + (threadIdx.x >> 5);
    int lane = threadIdx.x & 31;
    const float4* p = (const float4*)(x + (size_t)row * IN_DIM);
    __nv_bfloat162* q = (__nv_bfloat162*)(xb + (size_t)row * IN_DIM);
    float s = 0.f;
#pragma unroll
    for (int i = 0; i < IN_DIM / 128; i++) {
        float4 v = p[lane + i * 32];
        s += v.x * v.x + v.y * v.y + v.z * v.z + v.w * v.w;
        q[(lane + i * 32) * 2]     = __floats2bfloat162_rn(v.x, v.y);
        q[(lane + i * 32) * 2 + 1] = __floats2bfloat162_rn(v.z, v.w);
    }
#pragma unroll
    for (int o = 16; o; o >>= 1) s += __shfl_xor_sync(0xFFFFFFFFu, s, o);
    if (lane == 0) xsq[row] = s;
}

// ---------------------------------------------------------------------------
// Pre-pass 2: column sums of squares of W (fp32-exact)
// ---------------------------------------------------------------------------
__global__ void colsq_kernel(const float* __restrict__ w, float* __restrict__ wsq) {
    int o = blockIdx.x * blockDim.x + threadIdx.x;
    float s = 0.f;
#pragma unroll 16
    for (int i = 0; i < IN_DIM; i++) {
        float v = w[(size_t)i * OUT_DIM + o];
        s += v * v;
    }
    wsq[o] = s;
}

// ---------------------------------------------------------------------------
// Pre-pass 3: transpose W [IN, OUT] fp32 -> Wt [OUT, IN] bf16 (K-major B)
// ---------------------------------------------------------------------------
__global__ void transpose_w_kernel(const float* __restrict__ w,
                                   __nv_bfloat16* __restrict__ wt) {
    __shared__ float t[32][33];
    int o0 = blockIdx.x * 32, i0 = blockIdx.y * 32;
    int tx = threadIdx.x, ty = threadIdx.y;   // (32, 8)
#pragma unroll
    for (int j = 0; j < 4; j++)
        t[ty + 8 * j][tx] = w[(size_t)(i0 + ty + 8 * j) * OUT_DIM + o0 + tx];
    __syncthreads();
#pragma unroll
    for (int j = 0; j < 4; j++)
        wt[(size_t)(o0 + ty + 8 * j) * IN_DIM + i0 + tx] = __float2bfloat16(t[tx][ty + 8 * j]);
}

// ---------------------------------------------------------------------------
// Main kernel: 128x128 tile, mma.sync m16n8k16 bf16, 3-stage cp.async pipeline
// ---------------------------------------------------------------------------
#define BK          64
#define KITERS      (IN_DIM / BK)          // 16
#define OPER_BYTES  (128 * BK * 2)         // 16 KB per operand tile
#define STAGE_BYTES (2 * OPER_BYTES)       // 32 KB (A + B)
#define STAGES      3
#define SMEM_TOTAL  (STAGES * STAGE_BYTES) // 96 KB

// Issue one 128x64 bf16 tile (128B rows) with XOR-swizzled cp.async (4 chunks/thread)
__device__ __forceinline__ void issue_tile(uint32_t sdst, const __nv_bfloat16* g,
                                           int k0, int tid) {
#pragma unroll
    for (int i = 0; i < 4; i++) {
        int l   = tid + i * 256;
        int row = l >> 3;          // 0..127
        int c   = l & 7;           // 16B chunk within 128B row
        uint32_t off = (uint32_t)row * 128 + c * 16;
        uint32_t sw  = off ^ ((row & 7) << 4);
        cp16(sdst + sw, g + (size_t)row * IN_DIM + k0 + c * 8);
    }
}

__global__ __launch_bounds__(256)
void rbf_mma_kernel(const __nv_bfloat16* __restrict__ Xb,   // [B, IN]
                    const __nv_bfloat16* __restrict__ Wt,   // [OUT, IN]
                    const float* __restrict__ xsq,
                    const float* __restrict__ wsq,
                    float* __restrict__ out) {
    extern __shared__ char smem[];
    const uint32_t sb = smem_u32(smem);
    const int tid = threadIdx.x;
    const int lid = tid & 31, wid = tid >> 5;
    const int bx = blockIdx.x, by = blockIdx.y;

    const __nv_bfloat16* Ag = Xb + (size_t)(by * 128) * IN_DIM;
    const __nv_bfloat16* Bg = Wt + (size_t)(bx * 128) * IN_DIM;

    const int m0 = (wid >> 2) * 64;        // warp M offset within tile
    const int n0 = (wid & 3) * 32;         // warp N offset within tile

    float c[4][4][4];
#pragma unroll
    for (int mt = 0; mt < 4; mt++)
#pragma unroll
        for (int nt = 0; nt < 4; nt++)
#pragma unroll
            for (int i = 0; i < 4; i++) c[mt][nt][i] = 0.f;

    // Prologue: stages 0 and 1 in flight
    issue_tile(sb,                          Ag, 0, tid);
    issue_tile(sb + OPER_BYTES,             Bg, 0, tid);
    CP_COMMIT();
    issue_tile(sb + STAGE_BYTES,            Ag, BK, tid);
    issue_tile(sb + STAGE_BYTES + OPER_BYTES, Bg, BK, tid);
    CP_COMMIT();

    // Precomputed ldmatrix lane addressing
    const int arow_l  = lid & 15;                        // A: row within 16
    const uint32_t akh = (uint32_t)(lid >> 4) * 16;      // A: k-half byte offset
    const int brow_l  = (lid & 7) + ((lid >> 4) & 1) * 8;// B: row within 16
    const uint32_t bkh = (uint32_t)((lid >> 3) & 1) * 16;// B: k-half byte offset

    int stage = 0, pst = 2;
#pragma unroll 1
    for (int it = 0; it < KITERS; it++) {
        if (it + 1 < KITERS) { CP_WAIT(1); } else { CP_WAIT(0); }
        __syncthreads();

        if (it + 2 < KITERS) {
            uint32_t base = sb + pst * STAGE_BYTES;
            issue_tile(base,              Ag, (it + 2) * BK, tid);
            issue_tile(base + OPER_BYTES, Bg, (it + 2) * BK, tid);
            CP_COMMIT();
            pst = (pst == 2) ? 0 : pst + 1;
        }

        const uint32_t sA = sb + stage * STAGE_BYTES;
        const uint32_t sB = sA + OPER_BYTES;

#pragma unroll
        for (int ks = 0; ks < 4; ks++) {
            uint32_t a[16], b[8];
            const uint32_t kb = ks * 32;
#pragma unroll
            for (int mt = 0; mt < 4; mt++) {
                int r = m0 + mt * 16 + arow_l;
                uint32_t off = (uint32_t)r * 128 + kb + akh;
                ldsm_x4(a + mt * 4, sA + (off ^ ((r & 7) << 4)));
            }
#pragma unroll
            for (int nt2 = 0; nt2 < 2; nt2++) {
                int r = n0 + nt2 * 16 + brow_l;
                uint32_t off = (uint32_t)r * 128 + kb + bkh;
                ldsm_x4(b + nt2 * 4, sB + (off ^ ((r & 7) << 4)));
            }
#pragma unroll
            for (int mt = 0; mt < 4; mt++)
#pragma unroll
                for (int nt = 0; nt < 4; nt++)
                    mma16816(c[mt][nt], a + mt * 4, b + nt * 2);
        }
        stage = (stage == 2) ? 0 : stage + 1;
        __syncthreads();
    }

    // Fused epilogue: out = xsq + wsq - 2*acc (direct from fragments)
    const int n0g = bx * 128 + n0;
#pragma unroll
    for (int mt = 0; mt < 4; mt++) {
        int grow = by * 128 + m0 + mt * 16 + (lid >> 2);
        float xs0 = xsq[grow];
        float xs1 = xsq[grow + 8];
        float* r0 = out + (size_t)grow * OUT_DIM;
        float* r1 = out + (size_t)(grow + 8) * OUT_DIM;
#pragma unroll
        for (int nt = 0; nt < 4; nt++) {
            int gcol = n0g + nt * 8 + (lid & 3) * 2;
            float w0 = wsq[gcol], w1 = wsq[gcol + 1];
            float2 v0, v1;
            v0.x = xs0 + w0 - 2.f * c[mt][nt][0];
            v0.y = xs0 + w1 - 2.f * c[mt][nt][1];
            v1.x = xs1 + w0 - 2.f * c[mt][nt][2];
            v1.y = xs1 + w1 - 2.f * c[mt][nt][3];
            *(float2*)(r0 + gcol) = v0;
            *(float2*)(r1 + gcol) = v1;
        }
    }
}

// ---------------------------------------------------------------------------
extern "C" void kernel_launch(void* const* d_in, const int* in_sizes, int n_in,
                              void* d_out, int out_size) {
    const float* x = (const float*)d_in[0];
    const float* w = (const float*)d_in[1];
    float* out     = (float*)d_out;

    float *xsq, *wsq;
    __nv_bfloat16 *xb, *wt;
    cudaGetSymbolAddress((void**)&xsq, g_xsq);
    cudaGetSymbolAddress((void**)&wsq, g_wsq);
    cudaGetSymbolAddress((void**)&xb,  g_xb);
    cudaGetSymbolAddress((void**)&wt,  g_wt);

    rowsq_conv_kernel<<<B_DIM / 8, 256>>>(x, xsq, xb);
    colsq_kernel<<<OUT_DIM / 256, 256>>>(w, wsq);
    transpose_w_kernel<<<dim3(OUT_DIM / 32, IN_DIM / 32), dim3(32, 8)>>>(w, wt);

    cudaFuncSetAttribute(rbf_mma_kernel, cudaFuncAttributeMaxDynamicSharedMemorySize, SMEM_TOTAL);
    dim3 grid(OUT_DIM / 128, B_DIM / 128);   // 32 x 64
    rbf_mma_kernel<<<grid, 256, SMEM_TOTAL>>>(xb, wt, xsq, wsq, out);
}

// round 5
// speedup vs baseline: 6.9387x; 1.0998x over previous
#include <cuda_runtime.h>
#include <cuda_bf16.h>
#include <stdint.h>

#define B_DIM   8192
#define IN_DIM  1024
#define OUT_DIM 4096

// out[b,o] = ||x_b||^2 - 2 * (x @ W)[b,o] + ||w_:,o||^2

// ---------------------------------------------------------------------------
// Static device scratch (no cudaMalloc allowed)
// ---------------------------------------------------------------------------
#define WPARTS 16
__device__ float         g_xsq[B_DIM];
__device__ float         g_wsq[OUT_DIM];
__device__ float         g_wpart[WPARTS][OUT_DIM];
__device__ __nv_bfloat16 g_xb[(size_t)B_DIM * IN_DIM];    // X in bf16    (16 MB)
__device__ __nv_bfloat16 g_wt[(size_t)OUT_DIM * IN_DIM];  // W^T in bf16  ( 8 MB)

// ---------------------------------------------------------------------------
// Helpers (plain sm_80+ PTX only — compute_103 path rejects tcgen05)
// ---------------------------------------------------------------------------
__device__ __forceinline__ uint32_t smem_u32(const void* p) {
    uint32_t a;
    asm("{ .reg .u64 t; cvta.to.shared.u64 t, %1; cvt.u32.u64 %0, t; }" : "=r"(a) : "l"(p));
    return a;
}
__device__ __forceinline__ void cp16(uint32_t dst, const void* src) {
    asm volatile("cp.async.cg.shared.global [%0], [%1], 16;" :: "r"(dst), "l"(src));
}
#define CP_COMMIT() asm volatile("cp.async.commit_group;" ::: "memory")
#define CP_WAIT(n)  asm volatile("cp.async.wait_group %0;" :: "n"(n) : "memory")

__device__ __forceinline__ void ldsm_x4(uint32_t* r, uint32_t addr) {
    asm volatile("ldmatrix.sync.aligned.m8n8.x4.shared.b16 {%0,%1,%2,%3}, [%4];"
                 : "=r"(r[0]), "=r"(r[1]), "=r"(r[2]), "=r"(r[3]) : "r"(addr));
}
__device__ __forceinline__ void mma16816(float* c, const uint32_t* a, const uint32_t* b) {
    asm volatile("mma.sync.aligned.m16n8k16.row.col.f32.bf16.bf16.f32 "
                 "{%0,%1,%2,%3}, {%4,%5,%6,%7}, {%8,%9}, {%0,%1,%2,%3};"
                 : "+f"(c[0]), "+f"(c[1]), "+f"(c[2]), "+f"(c[3])
                 : "r"(a[0]), "r"(a[1]), "r"(a[2]), "r"(a[3]), "r"(b[0]), "r"(b[1]));
}

// ---------------------------------------------------------------------------
// Pre-pass 1: row sums of squares of x (fp32-exact) + convert x -> bf16
// ---------------------------------------------------------------------------
__global__ void rowsq_conv_kernel(const float* __restrict__ x,
                                  float* __restrict__ xsq,
                                  __nv_bfloat16* __restrict__ xb) {
    int row  = blockIdx.x * 8 + (threadIdx.x >> 5);
    int lane = threadIdx.x & 31;
    const float4* p = (const float4*)(x + (size_t)row * IN_DIM);
    __nv_bfloat162* q = (__nv_bfloat162*)(xb + (size_t)row * IN_DIM);
    float s = 0.f;
#pragma unroll
    for (int i = 0; i < IN_DIM / 128; i++) {
        float4 v = p[lane + i * 32];
        s += v.x * v.x + v.y * v.y + v.z * v.z + v.w * v.w;
        q[(lane + i * 32) * 2]     = __floats2bfloat162_rn(v.x, v.y);
        q[(lane + i * 32) * 2 + 1] = __floats2bfloat162_rn(v.z, v.w);
    }
#pragma unroll
    for (int o = 16; o; o >>= 1) s += __shfl_xor_sync(0xFFFFFFFFu, s, o);
    if (lane == 0) xsq[row] = s;
}

// ---------------------------------------------------------------------------
// Pre-pass 2: column sums of squares of W, two-phase deterministic reduce
// ---------------------------------------------------------------------------
__global__ void colsq_part_kernel(const float* __restrict__ w,
                                  float* __restrict__ wpart) {
    int o  = blockIdx.x * blockDim.x + threadIdx.x;   // 0..4095
    int p  = blockIdx.y;                              // 0..WPARTS-1
    int i0 = p * (IN_DIM / WPARTS);
    float s = 0.f;
#pragma unroll 8
    for (int i = 0; i < IN_DIM / WPARTS; i++) {
        float v = w[(size_t)(i0 + i) * OUT_DIM + o];
        s += v * v;
    }
    wpart[p * OUT_DIM + o] = s;
}
__global__ void colsq_reduce_kernel(const float* __restrict__ wpart,
                                    float* __restrict__ wsq) {
    int o = blockIdx.x * blockDim.x + threadIdx.x;
    float s = 0.f;
#pragma unroll
    for (int p = 0; p < WPARTS; p++) s += wpart[p * OUT_DIM + o];
    wsq[o] = s;
}

// ---------------------------------------------------------------------------
// Pre-pass 3: transpose W [IN, OUT] fp32 -> Wt [OUT, IN] bf16 (K-major B)
// ---------------------------------------------------------------------------
__global__ void transpose_w_kernel(const float* __restrict__ w,
                                   __nv_bfloat16* __restrict__ wt) {
    __shared__ float t[32][33];
    int o0 = blockIdx.x * 32, i0 = blockIdx.y * 32;
    int tx = threadIdx.x, ty = threadIdx.y;   // (32, 8)
#pragma unroll
    for (int j = 0; j < 4; j++)
        t[ty + 8 * j][tx] = w[(size_t)(i0 + ty + 8 * j) * OUT_DIM + o0 + tx];
    __syncthreads();
#pragma unroll
    for (int j = 0; j < 4; j++)
        wt[(size_t)(o0 + ty + 8 * j) * IN_DIM + i0 + tx] = __float2bfloat16(t[tx][ty + 8 * j]);
}

// ---------------------------------------------------------------------------
// Main kernel: CTA 128x256, warp tile 64x64 (2x4 warps), BK=64, 3-stage cp.async
// ---------------------------------------------------------------------------
#define BK          64
#define KITERS      (IN_DIM / BK)               // 16
#define BM          128
#define BN          256
#define A_BYTES     (BM * BK * 2)               // 16 KB
#define B_BYTES     (BN * BK * 2)               // 32 KB
#define STAGE_BYTES (A_BYTES + B_BYTES)         // 48 KB
#define STAGES      3
#define SMEM_TOTAL  (STAGES * STAGE_BYTES)      // 144 KB

// Fill ROWS x 64 bf16 tile (128B rows, XOR swizzle) with cp.async
template <int ROWS>
__device__ __forceinline__ void issue_tile(uint32_t sdst, const __nv_bfloat16* g,
                                           int k0, int tid) {
#pragma unroll
    for (int i = 0; i < ROWS * 8 / 256; i++) {
        int l   = tid + i * 256;
        int row = l >> 3;
        int c   = l & 7;
        uint32_t off = (uint32_t)row * 128 + c * 16;
        uint32_t sw  = off ^ ((row & 7) << 4);
        cp16(sdst + sw, g + (size_t)row * IN_DIM + k0 + c * 8);
    }
}

__global__ __launch_bounds__(256, 1)
void rbf_mma_kernel(const __nv_bfloat16* __restrict__ Xb,   // [B, IN]
                    const __nv_bfloat16* __restrict__ Wt,   // [OUT, IN]
                    const float* __restrict__ xsq,
                    const float* __restrict__ wsq,
                    float* __restrict__ out) {
    extern __shared__ char smem[];
    const uint32_t sb = smem_u32(smem);
    const int tid = threadIdx.x;
    const int lid = tid & 31, wid = tid >> 5;
    const int bx = blockIdx.x, by = blockIdx.y;

    const __nv_bfloat16* Ag = Xb + (size_t)(by * BM) * IN_DIM;
    const __nv_bfloat16* Bg = Wt + (size_t)(bx * BN) * IN_DIM;

    const int m0 = (wid >> 2) * 64;        // warp M offset (0 or 64)
    const int n0 = (wid & 3) * 64;         // warp N offset (0,64,128,192)

    float c[4][8][4];
#pragma unroll
    for (int mt = 0; mt < 4; mt++)
#pragma unroll
        for (int nt = 0; nt < 8; nt++)
#pragma unroll
            for (int i = 0; i < 4; i++) c[mt][nt][i] = 0.f;

    // Prologue: stages 0 and 1 in flight
    issue_tile<BM>(sb,                         Ag, 0, tid);
    issue_tile<BN>(sb + A_BYTES,               Bg, 0, tid);
    CP_COMMIT();
    issue_tile<BM>(sb + STAGE_BYTES,           Ag, BK, tid);
    issue_tile<BN>(sb + STAGE_BYTES + A_BYTES, Bg, BK, tid);
    CP_COMMIT();

    // ldmatrix lane addressing
    const int arow_l   = lid & 15;
    const uint32_t akh = (uint32_t)(lid >> 4) * 16;
    const int brow_l   = (lid & 7) + ((lid >> 4) & 1) * 8;
    const uint32_t bkh = (uint32_t)((lid >> 3) & 1) * 16;

    int stage = 0, pst = 2;
#pragma unroll 1
    for (int it = 0; it < KITERS; it++) {
        if (it + 1 < KITERS) { CP_WAIT(1); } else { CP_WAIT(0); }
        __syncthreads();

        if (it + 2 < KITERS) {
            uint32_t base = sb + pst * STAGE_BYTES;
            issue_tile<BM>(base,           Ag, (it + 2) * BK, tid);
            issue_tile<BN>(base + A_BYTES, Bg, (it + 2) * BK, tid);
            CP_COMMIT();
            pst = (pst == 2) ? 0 : pst + 1;
        }

        const uint32_t sA = sb + stage * STAGE_BYTES;
        const uint32_t sB = sA + A_BYTES;

#pragma unroll
        for (int ks = 0; ks < 4; ks++) {
            uint32_t a[16], b[16];
            const uint32_t kb = ks * 32;
#pragma unroll
            for (int mt = 0; mt < 4; mt++) {
                int r = m0 + mt * 16 + arow_l;
                uint32_t off = (uint32_t)r * 128 + kb + akh;
                ldsm_x4(a + mt * 4, sA + (off ^ ((r & 7) << 4)));
            }
#pragma unroll
            for (int nt2 = 0; nt2 < 4; nt2++) {
                int r = n0 + nt2 * 16 + brow_l;
                uint32_t off = (uint32_t)r * 128 + kb + bkh;
                ldsm_x4(b + nt2 * 4, sB + (off ^ ((r & 7) << 4)));
            }
#pragma unroll
            for (int mt = 0; mt < 4; mt++)
#pragma unroll
                for (int nt = 0; nt < 8; nt++)
                    mma16816(c[mt][nt], a + mt * 4, b + nt * 2);
        }
        stage = (stage == 2) ? 0 : stage + 1;
        // no trailing __syncthreads: stage reuse distance (3) is ordered by the
        // top-of-loop CP_WAIT + __syncthreads of later iterations
    }

    // Fused epilogue: out = xsq + wsq - 2*acc
    const int n0g = bx * BN + n0;
#pragma unroll
    for (int mt = 0; mt < 4; mt++) {
        int grow = by * BM + m0 + mt * 16 + (lid >> 2);
        float xs0 = xsq[grow];
        float xs1 = xsq[grow + 8];
        float* r0 = out + (size_t)grow * OUT_DIM;
        float* r1 = out + (size_t)(grow + 8) * OUT_DIM;
#pragma unroll
        for (int nt = 0; nt < 8; nt++) {
            int gcol = n0g + nt * 8 + (lid & 3) * 2;
            float w0 = wsq[gcol], w1 = wsq[gcol + 1];
            float2 v0, v1;
            v0.x = xs0 + w0 - 2.f * c[mt][nt][0];
            v0.y = xs0 + w1 - 2.f * c[mt][nt][1];
            v1.x = xs1 + w0 - 2.f * c[mt][nt][2];
            v1.y = xs1 + w1 - 2.f * c[mt][nt][3];
            *(float2*)(r0 + gcol) = v0;
            *(float2*)(r1 + gcol) = v1;
        }
    }
}

// ---------------------------------------------------------------------------
extern "C" void kernel_launch(void* const* d_in, const int* in_sizes, int n_in,
                              void* d_out, int out_size) {
    const float* x = (const float*)d_in[0];
    const float* w = (const float*)d_in[1];
    float* out     = (float*)d_out;

    float *xsq, *wsq, *wpart;
    __nv_bfloat16 *xb, *wt;
    cudaGetSymbolAddress((void**)&xsq,   g_xsq);
    cudaGetSymbolAddress((void**)&wsq,   g_wsq);
    cudaGetSymbolAddress((void**)&wpart, g_wpart);
    cudaGetSymbolAddress((void**)&xb,    g_xb);
    cudaGetSymbolAddress((void**)&wt,    g_wt);

    rowsq_conv_kernel<<<B_DIM / 8, 256>>>(x, xsq, xb);
    colsq_part_kernel<<<dim3(OUT_DIM / 256, WPARTS), 256>>>(w, wpart);
    colsq_reduce_kernel<<<OUT_DIM / 256, 256>>>(wpart, wsq);
    transpose_w_kernel<<<dim3(OUT_DIM / 32, IN_DIM / 32), dim3(32, 8)>>>(w, wt);

    cudaFuncSetAttribute(rbf_mma_kernel, cudaFuncAttributeMaxDynamicSharedMemorySize, SMEM_TOTAL);
    dim3 grid(OUT_DIM / BN, B_DIM / BM);   // 16 x 64 = 1024 blocks
    rbf_mma_kernel<<<grid, 256, SMEM_TOTAL>>>(xb, wt, xsq, wsq, out);
}